// round 12
// baseline (speedup 1.0000x reference)
#include <cuda_runtime.h>
#include <cstddef>

#define B_      128
#define NNZ_    128
#define H_      128
#define KOUT_   4096
#define FDIM_   135909

// Intermediate val1 [B, H] — device global scratch (no allocations allowed).
__device__ float g_val1[B_ * H_];

// ---------------------------------------------------------------------------
// Layer 1 (R1-exact: measured optimum, L1tex-wavefront / 64B-atom bound):
// val1[b,h] = relu( sum_i v[b,i] * W1[h, fidx[b,i]] + b1[h] )
// One block per b, 128 threads = one per h; indices/values staged in smem;
// i-loop unrolled x16 so ~16 independent gathers are in flight per thread.
// ---------------------------------------------------------------------------
__global__ __launch_bounds__(128) void layer1_kernel(
    const float* __restrict__ inv,
    const int*   __restrict__ fidx,
    const float* __restrict__ W1,
    const float* __restrict__ b1)
{
    const int b = blockIdx.x;
    const int h = threadIdx.x;

    __shared__ int   sidx[NNZ_];
    __shared__ float sval[NNZ_];
    sidx[h] = fidx[(b << 7) + h];
    sval[h] = inv[(b << 7) + h];
    __syncthreads();

    const float* w = W1 + (size_t)h * FDIM_;
    float acc = b1[h];

    #pragma unroll
    for (int i0 = 0; i0 < NNZ_; i0 += 16) {
        float wv[16];
        #pragma unroll
        for (int j = 0; j < 16; j++) wv[j] = __ldg(w + sidx[i0 + j]);
        #pragma unroll
        for (int j = 0; j < 16; j++) acc = fmaf(sval[i0 + j], wv[j], acc);
    }

    g_val1[(b << 7) + h] = fmaxf(acc, 0.0f);
}

// ---------------------------------------------------------------------------
// Layer 2: val2[b,k] = <val1[b,:], W2[lab[b,k],:]> + b2[lab[b,k]]
// R10 shape (warp = 4 outputs, 4 coalesced 512B row loads in flight, grid =
// (B*KOUT)/32 = 16384) with two critical-path cuts:
//  - labels: ONE uniform int4 load per warp (broadcast wavefront, no shfl)
//    instead of 4 scalar loads -> W2 addresses ready off a single load.
//  - val1: direct __ldg per lane (64KB table, L1/L2-hot, reused by 128
//    blocks per b) -> no smem staging, NO __syncthreads, warps independent
//    from instruction 0.
//  - bias gather issued before the shfl reduces (R10 win, kept).
// ---------------------------------------------------------------------------
__global__ __launch_bounds__(256) void layer2_kernel(
    const int*   __restrict__ lab,
    const float* __restrict__ W2,
    const float* __restrict__ b2,
    float*       __restrict__ out,
    float*       __restrict__ out_lab)   // may be null
{
    const int warp  = threadIdx.x >> 5;
    const int lane  = threadIdx.x & 31;
    const int b     = blockIdx.x >> 7;                      // 128 blocks per b
    const int kbase = ((blockIdx.x & 127) << 5) + (warp << 2);
    const int base  = (b << 12) + kbase;

    // one uniform 16B label load: all 4 row indices at once
    const int4 r4 = __ldg(reinterpret_cast<const int4*>(lab + base));
    const int rows[4] = { r4.x, r4.y, r4.z, r4.w };

    // val1[b] lane-slice straight from L1/L2 (hot: 128 blocks reuse each row)
    const float4 sv = __ldg(reinterpret_cast<const float4*>(g_val1 + (b << 7)) + lane);

    float acc[4];
    #pragma unroll
    for (int j = 0; j < 4; j++) {
        const float4 wv = __ldg(reinterpret_cast<const float4*>(W2) +
                                ((size_t)rows[j] << 5) + lane);
        acc[j] = wv.x * sv.x + wv.y * sv.y + wv.z * sv.z + wv.w * sv.w;
    }

    // issue the bias gather before the reduces so it flies during the shfls
    float bias = (lane < 4) ? __ldg(b2 + rows[lane]) : 0.0f;

    #pragma unroll
    for (int j = 0; j < 4; j++) {
        #pragma unroll
        for (int o = 16; o > 0; o >>= 1)
            acc[j] += __shfl_xor_sync(0xffffffffu, acc[j], o);
    }

    if (lane < 4) {
        const int j = lane;
        out[base + j] = acc[j] + bias;
        if (out_lab) out_lab[base + j] = (float)rows[j];
    }
}

// ---------------------------------------------------------------------------
extern "C" void kernel_launch(void* const* d_in, const int* in_sizes, int n_in,
                              void* d_out, int out_size)
{
    const float* inv  = (const float*)d_in[0];   // in_values        [B, NNZ]
    const int*   fidx = (const int*)  d_in[1];   // active_in_indices[B, NNZ]
    const int*   lab  = (const int*)  d_in[2];   // active_label_idx [B, KOUT]
    const float* W1   = (const float*)d_in[3];   // [H, FDIM]
    const float* b1   = (const float*)d_in[4];   // [H]
    const float* W2   = (const float*)d_in[5];   // [C, H]
    const float* b2   = (const float*)d_in[6];   // [C]

    float* out = (float*)d_out;
    const int n_val2 = B_ * KOUT_;
    float* out_lab = (out_size >= 2 * n_val2) ? (out + n_val2) : nullptr;

    layer1_kernel<<<B_, 128>>>(inv, fidx, W1, b1);
    layer2_kernel<<<(B_ * KOUT_) / 32, 256>>>(lab, W2, b2, out, out_lab);
}

// round 13
// speedup vs baseline: 1.0373x; 1.0373x over previous
#include <cuda_runtime.h>
#include <cstddef>

#define B_      128
#define NNZ_    128
#define H_      128
#define KOUT_   4096
#define FDIM_   135909

// Intermediate val1 [B, H] — device global scratch (no allocations allowed).
__device__ float g_val1[B_ * H_];

// ---------------------------------------------------------------------------
// Layer 1 (measured optimum — at HBM 64B-atom spec for random 4B gathers):
// val1[b,h] = relu( sum_i v[b,i] * W1[h, fidx[b,i]] + b1[h] )
// One block per b, 128 threads = one per h; indices/values staged in smem;
// i-loop unrolled x16 so ~16 independent gathers are in flight per thread.
// ---------------------------------------------------------------------------
__global__ __launch_bounds__(128) void layer1_kernel(
    const float* __restrict__ inv,
    const int*   __restrict__ fidx,
    const float* __restrict__ W1,
    const float* __restrict__ b1)
{
    const int b = blockIdx.x;
    const int h = threadIdx.x;

    __shared__ int   sidx[NNZ_];
    __shared__ float sval[NNZ_];
    sidx[h] = fidx[(b << 7) + h];
    sval[h] = inv[(b << 7) + h];
    __syncthreads();

    const float* w = W1 + (size_t)h * FDIM_;
    float acc = b1[h];

    #pragma unroll
    for (int i0 = 0; i0 < NNZ_; i0 += 16) {
        float wv[16];
        #pragma unroll
        for (int j = 0; j < 16; j++) wv[j] = __ldg(w + sidx[i0 + j]);
        #pragma unroll
        for (int j = 0; j < 16; j++) acc = fmaf(sval[i0 + j], wv[j], acc);
    }

    g_val1[(b << 7) + h] = fmaxf(acc, 0.0f);
}

// ---------------------------------------------------------------------------
// Layer 2 (R11 shape — measured optimum):
//   val2[b,k] = <val1[b,:], W2[lab[b,k],:]> + b2[lab[b,k]]
// Warp = 4 outputs via 4 coalesced 512B W2-row loads in flight; no smem, no
// barriers; labels via ONE uniform int4 load; bias gather overlapped with the
// shfl reduce. Grid = (B*KOUT)/32 = 16384.
// NEW vs R11 (off-critical-path cache hints only):
//  - labels read with __ldcs  (2MB, read-once -> evict-first, keep W2 in L2)
//  - out / out_lab written with __stcs (4MB, write-once, never re-read)
// ---------------------------------------------------------------------------
__global__ __launch_bounds__(256) void layer2_kernel(
    const int*   __restrict__ lab,
    const float* __restrict__ W2,
    const float* __restrict__ b2,
    float*       __restrict__ out,
    float*       __restrict__ out_lab)   // may be null
{
    const int warp  = threadIdx.x >> 5;
    const int lane  = threadIdx.x & 31;
    const int b     = blockIdx.x >> 7;                      // 128 blocks per b
    const int kbase = ((blockIdx.x & 127) << 5) + (warp << 2);
    const int base  = (b << 12) + kbase;

    // one uniform 16B label load (broadcast wavefront), evict-first
    const int4 r4 = __ldcs(reinterpret_cast<const int4*>(lab + base));
    const int rows[4] = { r4.x, r4.y, r4.z, r4.w };

    // val1[b] lane-slice straight from L1/L2 (hot: 128 blocks reuse each row)
    const float4 sv = __ldg(reinterpret_cast<const float4*>(g_val1 + (b << 7)) + lane);

    float acc[4];
    #pragma unroll
    for (int j = 0; j < 4; j++) {
        const float4 wv = __ldg(reinterpret_cast<const float4*>(W2) +
                                ((size_t)rows[j] << 5) + lane);
        acc[j] = wv.x * sv.x + wv.y * sv.y + wv.z * sv.z + wv.w * sv.w;
    }

    // issue the bias gather before the reduces so it flies during the shfls
    float bias = (lane < 4) ? __ldg(b2 + rows[lane]) : 0.0f;

    #pragma unroll
    for (int j = 0; j < 4; j++) {
        #pragma unroll
        for (int o = 16; o > 0; o >>= 1)
            acc[j] += __shfl_xor_sync(0xffffffffu, acc[j], o);
    }

    if (lane < 4) {
        const int j = lane;
        __stcs(out + base + j, acc[j] + bias);
        if (out_lab) __stcs(out_lab + base + j, (float)rows[j]);
    }
}

// ---------------------------------------------------------------------------
extern "C" void kernel_launch(void* const* d_in, const int* in_sizes, int n_in,
                              void* d_out, int out_size)
{
    const float* inv  = (const float*)d_in[0];   // in_values        [B, NNZ]
    const int*   fidx = (const int*)  d_in[1];   // active_in_indices[B, NNZ]
    const int*   lab  = (const int*)  d_in[2];   // active_label_idx [B, KOUT]
    const float* W1   = (const float*)d_in[3];   // [H, FDIM]
    const float* b1   = (const float*)d_in[4];   // [H]
    const float* W2   = (const float*)d_in[5];   // [C, H]
    const float* b2   = (const float*)d_in[6];   // [C]

    float* out = (float*)d_out;
    const int n_val2 = B_ * KOUT_;
    float* out_lab = (out_size >= 2 * n_val2) ? (out + n_val2) : nullptr;

    layer1_kernel<<<B_, 128>>>(inv, fidx, W1, b1);
    layer2_kernel<<<(B_ * KOUT_) / 32, 256>>>(lab, W2, b2, out, out_lab);
}